// round 2
// baseline (speedup 1.0000x reference)
#include <cuda_runtime.h>

#define NN   25000
#define EE   200000
#define HH   512
#define OUTC 250
#define LL   4
#define RR   3
#define KCAT (RR*HH + HH)   // 2048

// ---------------- scratch (device globals; no allocation allowed) ----------------
__device__ __align__(256) float g_t1[(size_t)NN*HH];
__device__ __align__(256) float g_h[(size_t)NN*HH];
__device__ __align__(256) float g_hcat[(size_t)NN*KCAT];
__device__ __align__(256) float g_Wcat[(size_t)LL*KCAT*HH];
__device__ __align__(256) float g_bsum[LL*HH];
__device__ __align__(256) float g_inv[RR*NN];
__device__ int   g_cnt[RR*NN];
__device__ int   g_off[RR*NN];
__device__ int   g_cur[RR*NN];
__device__ int   g_csr[RR*EE];

// ---------------- GEMM: C[M,N] = f( (A[M,K] @ B[K,N] + bias) * scale ) ----------------
// BM=128, BN=128, BK=16, 256 threads, 8x8 per thread. K must be a multiple of 16.
template<bool BVEC>
__global__ __launch_bounds__(256) void gemm_kernel(
    const float* __restrict__ A, const float* __restrict__ B,
    const float* __restrict__ bias, float* __restrict__ C,
    int M, int K, int N, int lda, float scale, int leaky)
{
    __shared__ __align__(16) float sA[16][128];
    __shared__ __align__(16) float sB[16][128];

    const int tid  = threadIdx.x;
    const int row0 = blockIdx.y * 128;
    const int col0 = blockIdx.x * 128;
    const int tr   = (tid >> 4) * 8;
    const int tc   = (tid & 15) * 8;

    // A loader: row = tid>>1 (0..127), kk = (tid&1)*8 -> two float4
    const int aRow = tid >> 1;
    const int aK   = (tid & 1) * 8;
    // B loader (vector): kB = tid>>5 (0..7), colB = (tid&31)*4 ; loads k=kB and kB+8
    const int kB   = tid >> 5;
    const int colB = (tid & 31) * 4;
    // B loader (scalar): kS = tid>>4 (0..15), colS = (tid&15)*8
    const int kS   = tid >> 4;
    const int colS = (tid & 15) * 8;

    float acc[8][8];
#pragma unroll
    for (int i = 0; i < 8; i++)
#pragma unroll
        for (int j = 0; j < 8; j++) acc[i][j] = 0.f;

    for (int k0 = 0; k0 < K; k0 += 16) {
        // ---- load A tile (row-guarded) ----
        {
            float4 a0 = {0,0,0,0}, a1 = {0,0,0,0};
            if (row0 + aRow < M) {
                const float* ap = A + (size_t)(row0 + aRow) * lda + k0 + aK;
                a0 = *(const float4*)(ap);
                a1 = *(const float4*)(ap + 4);
            }
            sA[aK+0][aRow] = a0.x; sA[aK+1][aRow] = a0.y;
            sA[aK+2][aRow] = a0.z; sA[aK+3][aRow] = a0.w;
            sA[aK+4][aRow] = a1.x; sA[aK+5][aRow] = a1.y;
            sA[aK+6][aRow] = a1.z; sA[aK+7][aRow] = a1.w;
        }
        // ---- load B tile ----
        if (BVEC) {
            const float4 b0 = *(const float4*)(B + (size_t)(k0 + kB) * N + col0 + colB);
            const float4 b1 = *(const float4*)(B + (size_t)(k0 + kB + 8) * N + col0 + colB);
            *(float4*)&sB[kB][colB]     = b0;
            *(float4*)&sB[kB + 8][colB] = b1;
        } else {
#pragma unroll
            for (int j = 0; j < 8; j++) {
                int c = col0 + colS + j;
                sB[kS][colS + j] = (c < N) ? B[(size_t)(k0 + kS) * N + c] : 0.f;
            }
        }
        __syncthreads();

#pragma unroll
        for (int kk = 0; kk < 16; kk++) {
            float a[8], b[8];
            *(float4*)(&a[0]) = *(const float4*)(&sA[kk][tr]);
            *(float4*)(&a[4]) = *(const float4*)(&sA[kk][tr + 4]);
            *(float4*)(&b[0]) = *(const float4*)(&sB[kk][tc]);
            *(float4*)(&b[4]) = *(const float4*)(&sB[kk][tc + 4]);
#pragma unroll
            for (int i = 0; i < 8; i++)
#pragma unroll
                for (int j = 0; j < 8; j++)
                    acc[i][j] = fmaf(a[i], b[j], acc[i][j]);
        }
        __syncthreads();
    }

    // ---- epilogue ----
#pragma unroll
    for (int i = 0; i < 8; i++) {
        int r = row0 + tr + i;
        if (r >= M) continue;
#pragma unroll
        for (int j = 0; j < 8; j++) {
            int c = col0 + tc + j;
            if (c >= N) continue;
            float v = acc[i][j];
            if (bias) v += bias[c];
            v *= scale;
            if (leaky) v = (v >= 0.f) ? v : 0.2f * v;
            C[(size_t)r * N + c] = v;
        }
    }
}

// ---------------- graph preprocessing ----------------
__global__ void hist_kernel(const int* __restrict__ edges)
{
    int idx = blockIdx.x * blockDim.x + threadIdx.x;
    if (idx >= RR * EE) return;
    int r = idx / EE, e = idx % EE;
    int dst = edges[(r * 2 + 1) * EE + e];
    atomicAdd(&g_cnt[r * NN + dst], 1);
}

__global__ void scan_kernel()
{
    int r = blockIdx.x;
    __shared__ int sh[1024];
    __shared__ int s_run;
    if (threadIdx.x == 0) s_run = 0;
    __syncthreads();
    for (int base = 0; base < NN; base += 1024) {
        int i = base + threadIdx.x;
        int c = (i < NN) ? g_cnt[r * NN + i] : 0;
        sh[threadIdx.x] = c;
        __syncthreads();
        for (int d = 1; d < 1024; d <<= 1) {
            int v = (threadIdx.x >= d) ? sh[threadIdx.x - d] : 0;
            __syncthreads();
            sh[threadIdx.x] += v;
            __syncthreads();
        }
        int excl = sh[threadIdx.x] - c;
        if (i < NN) {
            int o = s_run + excl;
            g_off[r * NN + i] = o;
            g_cur[r * NN + i] = o;
            g_inv[r * NN + i] = 1.0f / fmaxf((float)c, 1.0f);
        }
        __syncthreads();
        if (threadIdx.x == 1023) s_run += sh[1023];
        __syncthreads();
    }
}

__global__ void fill_kernel(const int* __restrict__ edges)
{
    int idx = blockIdx.x * blockDim.x + threadIdx.x;
    if (idx >= RR * EE) return;
    int r = idx / EE, e = idx % EE;
    int src = edges[(r * 2 + 0) * EE + e];
    int dst = edges[(r * 2 + 1) * EE + e];
    int p = atomicAdd(&g_cur[r * NN + dst], 1);
    g_csr[r * EE + p] = src;
}

// ---------------- weight stacking ----------------
__global__ void wcat_build(const float* __restrict__ Wl, const float* __restrict__ Wr)
{
    int idx = blockIdx.x * blockDim.x + threadIdx.x;
    if (idx >= LL * KCAT * HH) return;
    int l   = idx / (KCAT * HH);
    int rem = idx % (KCAT * HH);
    int k   = rem / HH;
    int j   = rem % HH;
    float v;
    if (k < RR * HH) {
        int r = k / HH, kk = k % HH;
        v = Wl[(((size_t)l * RR + r) * HH + kk) * HH + j];
    } else {
        int kk = k - RR * HH;
        v = 0.f;
#pragma unroll
        for (int r = 0; r < RR; r++)
            v += Wr[(((size_t)l * RR + r) * HH + kk) * HH + j];
    }
    g_Wcat[idx] = v;
}

__global__ void bsum_build(const float* __restrict__ bl)
{
    int idx = blockIdx.x * blockDim.x + threadIdx.x;
    if (idx >= LL * HH) return;
    int l = idx / HH, j = idx % HH;
    float v = 0.f;
#pragma unroll
    for (int r = 0; r < RR; r++) v += bl[(l * RR + r) * HH + j];
    g_bsum[idx] = v;
}

// ---------------- per-layer ops ----------------
__global__ void copy_h_kernel()
{
    int idx = blockIdx.x * blockDim.x + threadIdx.x;   // over NN * (HH/4)
    if (idx >= NN * (HH / 4)) return;
    int row = idx / (HH / 4);
    int c   = idx % (HH / 4);
    *(float4*)(g_hcat + (size_t)row * KCAT + RR * HH + c * 4) =
        *(const float4*)(g_h + (size_t)row * HH + c * 4);
}

__global__ __launch_bounds__(128) void agg_kernel()
{
    int node = blockIdx.x;
    int r    = blockIdx.y;
    int t    = threadIdx.x;   // 128 threads, 4 floats each
    int base = r * NN + node;
    int b    = g_off[base];
    int d    = g_cnt[base];
    const int* lst = g_csr + (size_t)r * EE + b;
    float4 acc = {0.f, 0.f, 0.f, 0.f};
    for (int e = 0; e < d; e++) {
        int s = lst[e];
        const float4 v = *(const float4*)(g_h + (size_t)s * HH + t * 4);
        acc.x += v.x; acc.y += v.y; acc.z += v.z; acc.w += v.w;
    }
    float sc = g_inv[base];
    acc.x *= sc; acc.y *= sc; acc.z *= sc; acc.w *= sc;
    *(float4*)(g_hcat + (size_t)node * KCAT + r * HH + t * 4) = acc;
}

// ---------------- launch ----------------
extern "C" void kernel_launch(void* const* d_in, const int* in_sizes, int n_in,
                              void* d_out, int out_size)
{
    const float* x     = (const float*)d_in[0];
    const float* Wpre  = (const float*)d_in[1];
    const float* Wpost = (const float*)d_in[2];
    const float* Wl    = (const float*)d_in[3];
    const float* Wr    = (const float*)d_in[4];
    const float* bl    = (const float*)d_in[5];
    const float* Wout  = (const float*)d_in[6];
    const float* bout  = (const float*)d_in[7];
    const int*   edges = (const int*)d_in[8];
    float* out = (float*)d_out;

    float *t1, *h, *hcat, *Wcat, *bsum;
    int *cnt;
    cudaGetSymbolAddress((void**)&t1,   g_t1);
    cudaGetSymbolAddress((void**)&h,    g_h);
    cudaGetSymbolAddress((void**)&hcat, g_hcat);
    cudaGetSymbolAddress((void**)&Wcat, g_Wcat);
    cudaGetSymbolAddress((void**)&bsum, g_bsum);
    cudaGetSymbolAddress((void**)&cnt,  g_cnt);

    // weight stacking (tiny)
    wcat_build<<<(LL * KCAT * HH + 255) / 256, 256>>>(Wl, Wr);
    bsum_build<<<(LL * HH + 255) / 256, 256>>>(bl);

    // pre/post transforms: h = leaky(leaky(x@Wpre)@Wpost)
    dim3 g512((HH + 127) / 128, (NN + 127) / 128);
    gemm_kernel<true><<<g512, 256>>>(x,  Wpre,  nullptr, t1, NN, HH, HH, HH, 1.f, 1);
    gemm_kernel<true><<<g512, 256>>>(t1, Wpost, nullptr, h,  NN, HH, HH, HH, 1.f, 1);

    // CSR build (once per call; reused by all 4 layers)
    cudaMemsetAsync(cnt, 0, (size_t)RR * NN * sizeof(int));
    hist_kernel<<<(RR * EE + 255) / 256, 256>>>(edges);
    scan_kernel<<<RR, 1024>>>();
    fill_kernel<<<(RR * EE + 255) / 256, 256>>>(edges);

    // layers
    for (int l = 0; l < LL; l++) {
        copy_h_kernel<<<(NN * (HH / 4) + 255) / 256, 256>>>();
        dim3 ga(NN, RR);
        agg_kernel<<<ga, 128>>>();
        gemm_kernel<true><<<g512, 256>>>(hcat, Wcat + (size_t)l * KCAT * HH,
                                         bsum + l * HH, h,
                                         NN, KCAT, HH, KCAT, 1.f / 3.f, 1);
    }

    // output projection
    dim3 gout((OUTC + 127) / 128, (NN + 127) / 128);
    gemm_kernel<false><<<gout, 256>>>(h, Wout, bout, out, NN, HH, OUTC, HH, 1.f, 0);
}

// round 4
// speedup vs baseline: 2.0929x; 2.0929x over previous
#include <cuda_runtime.h>
#include <cuda_bf16.h>
#include <cstdint>

#define NN    25000
#define EE    200000
#define HH    512
#define OUTC  250
#define LL    4
#define RR    3
#define MT    196
#define MPAD  (MT*128)        // 25088
#define KCAT  2048
#define NSTG  3
#define TILE8 8192            // one 128x32 bf16 tile in smem (bytes)
#define STAGEB (4*TILE8)      // Ahi, Alo, Bhi, Blo
#define SMEM_SZ (NSTG*STAGEB) // 98304

typedef __nv_bfloat16 bf16;

// ---------------- device scratch (zero-init .bss; pad rows stay zero) ----------------
__device__ __align__(256) bf16 g_xh [(size_t)MPAD*HH];
__device__ __align__(256) bf16 g_xl [(size_t)MPAD*HH];
__device__ __align__(256) bf16 g_t1h[(size_t)MPAD*HH];
__device__ __align__(256) bf16 g_t1l[(size_t)MPAD*HH];
__device__ __align__(256) bf16 g_Ph [(size_t)MPAD*KCAT];
__device__ __align__(256) bf16 g_Pl [(size_t)MPAD*KCAT];
__device__ __align__(256) bf16 g_Qh [(size_t)MPAD*KCAT];
__device__ __align__(256) bf16 g_Ql [(size_t)MPAD*KCAT];
__device__ __align__(256) bf16 g_wpreh [(size_t)HH*HH];
__device__ __align__(256) bf16 g_wprel [(size_t)HH*HH];
__device__ __align__(256) bf16 g_wposth[(size_t)HH*HH];
__device__ __align__(256) bf16 g_wpostl[(size_t)HH*HH];
__device__ __align__(256) bf16 g_wcath [(size_t)LL*HH*KCAT];
__device__ __align__(256) bf16 g_wcatl [(size_t)LL*HH*KCAT];
__device__ __align__(256) bf16 g_wouth [(size_t)256*HH];
__device__ __align__(256) bf16 g_woutl [(size_t)256*HH];
__device__ __align__(256) float g_bsum[LL*HH];
__device__ __align__(256) float g_inv[RR*NN];
__device__ int g_cnt[RR*NN];
__device__ int g_off[RR*NN];
__device__ int g_cur[RR*NN];
__device__ int g_csr[RR*EE];

// ---------------- helpers ----------------
__device__ __forceinline__ uint32_t s2u(const void* p){ return (uint32_t)__cvta_generic_to_shared(p); }
__device__ __forceinline__ void cpa16(uint32_t s, const void* g){
    asm volatile("cp.async.cg.shared.global [%0], [%1], 16;" :: "r"(s), "l"(g));
}
__device__ __forceinline__ void cp_commit(){ asm volatile("cp.async.commit_group;"); }
__device__ __forceinline__ void cp_wait1(){ asm volatile("cp.async.wait_group 1;"); }
__device__ __forceinline__ void cp_wait0(){ asm volatile("cp.async.wait_group 0;"); }
__device__ __forceinline__ void ldsm4(uint32_t* r, uint32_t a){
    asm volatile("ldmatrix.sync.aligned.m8n8.x4.shared.b16 {%0,%1,%2,%3}, [%4];"
                 : "=r"(r[0]),"=r"(r[1]),"=r"(r[2]),"=r"(r[3]) : "r"(a));
}
__device__ __forceinline__ void mma16816(float* c, const uint32_t* a, uint32_t b0, uint32_t b1){
    asm volatile("mma.sync.aligned.m16n8k16.row.col.f32.bf16.bf16.f32 "
                 "{%0,%1,%2,%3}, {%4,%5,%6,%7}, {%8,%9}, {%0,%1,%2,%3};"
                 : "+f"(c[0]),"+f"(c[1]),"+f"(c[2]),"+f"(c[3])
                 : "r"(a[0]),"r"(a[1]),"r"(a[2]),"r"(a[3]), "r"(b0),"r"(b1));
}
__device__ __forceinline__ uint32_t packbf2(float a, float b){
    __nv_bfloat162 t = __floats2bfloat162_rn(a, b);
    return *reinterpret_cast<uint32_t*>(&t);
}
__device__ __forceinline__ float bfhi(float a){ return __bfloat162float(__float2bfloat16(a)); }
// smem tile byte offset with XOR swizzle (row stride 64B, 4x 16B units)
__device__ __forceinline__ uint32_t swoff(int m, int ku){
    return (uint32_t)(m*64 + ((ku ^ ((m>>1)&3)) << 4));
}

// ------------------------------------------------------------------
// bf16 split GEMM: C[M,N] = f((Ah+Al)[M,K] @ (Bh+Bl)^T, bias, scale, leaky)
// A: row-major [.,lda] bf16 hi/lo ; B: W^T row-major [Npad][K] hi/lo
// optional dH/dL bf16 hi/lo output (at dcol0, ldd) and/or fp32 cOut [M,cN]
// grid: (N/128, MT), 256 threads
// ------------------------------------------------------------------
__global__ __launch_bounds__(256,1) void tc_gemm(
    const bf16* __restrict__ aH, const bf16* __restrict__ aL, int lda,
    const bf16* __restrict__ bH, const bf16* __restrict__ bL, int K,
    const float* __restrict__ bias, int biasN, float scale, int leaky,
    bf16* __restrict__ dH, bf16* __restrict__ dL, int ldd, int dcol0,
    float* __restrict__ cOut, int cN, int M)
{
    extern __shared__ __align__(128) uint8_t smem[];
    const uint32_t sb = s2u(smem);
    const int tid = threadIdx.x, lane = tid & 31, wid = tid >> 5;
    const int wm = wid & 3, wn = wid >> 2;      // 4 warps in M, 2 in N
    const int nt = blockIdx.x, mt = blockIdx.y;
    const int KT = K >> 5;

    const bf16* base0 = aH + (size_t)mt*128*lda;
    const bf16* base1 = aL + (size_t)mt*128*lda;
    const bf16* base2 = bH + (size_t)nt*128*K;
    const bf16* base3 = bL + (size_t)nt*128*K;

    // stage loader: 2048 x 16B units; unit u -> tile u>>9, m=(u>>2)&127, ku=u&3
    auto load_stage = [&](int kt, int s){
        const int k0 = kt*32;
        #pragma unroll
        for (int i = 0; i < 8; i++){
            const int u  = tid + i*256;
            const int t4 = i >> 1;                 // constant per i
            const int m  = (u >> 2) & 127;
            const int ku = u & 3;
            uint32_t sa = sb + s*STAGEB + t4*TILE8 + swoff(m, ku);
            const bf16* src;
            if      (t4 == 0) src = base0 + (size_t)m*lda + k0 + ku*8;
            else if (t4 == 1) src = base1 + (size_t)m*lda + k0 + ku*8;
            else if (t4 == 2) src = base2 + (size_t)m*K   + k0 + ku*8;
            else              src = base3 + (size_t)m*K   + k0 + ku*8;
            cpa16(sa, src);
        }
    };

    float acc[2][8][4];
    #pragma unroll
    for (int a = 0; a < 2; a++)
    #pragma unroll
    for (int b = 0; b < 8; b++)
    #pragma unroll
    for (int c = 0; c < 4; c++) acc[a][b][c] = 0.f;

    load_stage(0, 0); cp_commit();
    load_stage(1, 1); cp_commit();

    for (int kt = 0; kt < KT; kt++){
        const int s = kt % NSTG;
        if (kt < KT-1) cp_wait1(); else cp_wait0();
        __syncthreads();

        const uint32_t sA = sb + s*STAGEB;
        const uint32_t sB = sA + 2*TILE8;
        #pragma unroll
        for (int kk = 0; kk < 2; kk++){            // two k16 per BK32
            const int kub = kk*2 + (lane >> 4);
            uint32_t ah[2][4], al[2][4];
            #pragma unroll
            for (int mi = 0; mi < 2; mi++){
                const int m = wm*32 + mi*16 + (lane & 15);
                const uint32_t a = sA + swoff(m, kub);
                ldsm4(ah[mi], a);
                ldsm4(al[mi], a + TILE8);
            }
            uint32_t bh[4][4], bl[4][4];
            #pragma unroll
            for (int g = 0; g < 4; g++){
                const int n = wn*64 + g*16 + (lane & 15);
                const uint32_t a = sB + swoff(n, kub);
                ldsm4(bh[g], a);
                ldsm4(bl[g], a + TILE8);
            }
            #pragma unroll
            for (int mi = 0; mi < 2; mi++)
            #pragma unroll
            for (int g = 0; g < 4; g++){
                // n-tile 2g: frag {r0,r2}; n-tile 2g+1: frag {r1,r3}
                mma16816(acc[mi][2*g],   ah[mi], bh[g][0], bh[g][2]);
                mma16816(acc[mi][2*g],   ah[mi], bl[g][0], bl[g][2]);
                mma16816(acc[mi][2*g],   al[mi], bh[g][0], bh[g][2]);
                mma16816(acc[mi][2*g+1], ah[mi], bh[g][1], bh[g][3]);
                mma16816(acc[mi][2*g+1], ah[mi], bl[g][1], bl[g][3]);
                mma16816(acc[mi][2*g+1], al[mi], bh[g][1], bh[g][3]);
            }
        }
        __syncthreads();
        if (kt + 2 < KT){ load_stage(kt+2, (kt+2)%NSTG); cp_commit(); }
    }

    // ---- epilogue ----
    #pragma unroll
    for (int mi = 0; mi < 2; mi++)
    #pragma unroll
    for (int rg = 0; rg < 2; rg++){
        const int m = mt*128 + wm*32 + mi*16 + rg*8 + (lane >> 2);
        if (m >= M) continue;
        #pragma unroll
        for (int nj = 0; nj < 8; nj++){
            const int col = nt*128 + wn*64 + nj*8 + (lane & 3)*2;
            float v0 = acc[mi][nj][rg*2+0];
            float v1 = acc[mi][nj][rg*2+1];
            if (bias){
                if (col   < biasN) v0 += __ldg(bias + col);
                if (col+1 < biasN) v1 += __ldg(bias + col + 1);
            }
            v0 *= scale; v1 *= scale;
            if (leaky){
                v0 = (v0 >= 0.f) ? v0 : 0.2f*v0;
                v1 = (v1 >= 0.f) ? v1 : 0.2f*v1;
            }
            if (cOut){
                if (col   < cN) cOut[(size_t)m*cN + col]     = v0;
                if (col+1 < cN) cOut[(size_t)m*cN + col + 1] = v1;
            }
            if (dH){
                const float h0 = bfhi(v0), h1 = bfhi(v1);
                *(uint32_t*)(dH + (size_t)m*ldd + dcol0 + col) = packbf2(h0, h1);
                *(uint32_t*)(dL + (size_t)m*ldd + dcol0 + col) = packbf2(v0 - h0, v1 - h1);
            }
        }
    }
}

// ---------------- packing kernels ----------------
__global__ void conv_x(const float* __restrict__ x)
{
    int idx = blockIdx.x*blockDim.x + threadIdx.x;     // NN*128
    if (idx >= NN*128) return;
    int n = idx >> 7, c = (idx & 127)*4;
    const float4 v = *(const float4*)(x + (size_t)n*HH + c);
    float h0 = bfhi(v.x), h1 = bfhi(v.y), h2 = bfhi(v.z), h3 = bfhi(v.w);
    uint2 hw = make_uint2(packbf2(h0,h1), packbf2(h2,h3));
    uint2 lw = make_uint2(packbf2(v.x-h0, v.y-h1), packbf2(v.z-h2, v.w-h3));
    *(uint2*)(g_xh + (size_t)n*HH + c) = hw;
    *(uint2*)(g_xl + (size_t)n*HH + c) = lw;
}

// W [K][Nw] fp32 -> W^T [Npad][K] bf16 hi/lo (zero pad rows)
__global__ void wb_t(const float* __restrict__ W, bf16* __restrict__ dh, bf16* __restrict__ dl,
                     int K, int Nw, int Npad)
{
    int idx = blockIdx.x*blockDim.x + threadIdx.x;     // Npad*K/2
    if (idx >= Npad*(K/2)) return;
    int k = (idx % (K/2))*2, n = idx / (K/2);
    float v0 = 0.f, v1 = 0.f;
    if (n < Nw){ v0 = W[(size_t)k*Nw + n]; v1 = W[(size_t)(k+1)*Nw + n]; }
    float h0 = bfhi(v0), h1 = bfhi(v1);
    *(uint32_t*)(dh + (size_t)n*K + k) = packbf2(h0, h1);
    *(uint32_t*)(dl + (size_t)n*K + k) = packbf2(v0-h0, v1-h1);
}

// Wcat^T [l][512 n][2048 k]: k<1536 -> Wl[l][k/512][k%512][n]; else sum_r Wr[l][r][k-1536][n]
__global__ void wb_cat(const float* __restrict__ Wl, const float* __restrict__ Wr)
{
    int idx = blockIdx.x*blockDim.x + threadIdx.x;     // LL*512*1024
    if (idx >= LL*HH*(KCAT/2)) return;
    int k = (idx & 1023)*2, n = (idx >> 10) & 511, l = idx >> 19;
    float v[2];
    #pragma unroll
    for (int q = 0; q < 2; q++){
        int kq = k + q;
        if (kq < RR*HH){
            int r = kq / HH, kk = kq % HH;
            v[q] = Wl[((((size_t)l*RR + r)*HH + kk)*HH) + n];
        } else {
            int kk = kq - RR*HH;
            float s = 0.f;
            #pragma unroll
            for (int r = 0; r < RR; r++)
                s += Wr[((((size_t)l*RR + r)*HH + kk)*HH) + n];
            v[q] = s;
        }
    }
    float h0 = bfhi(v[0]), h1 = bfhi(v[1]);
    size_t o = ((size_t)l*HH + n)*KCAT + k;
    *(uint32_t*)(g_wcath + o) = packbf2(h0, h1);
    *(uint32_t*)(g_wcatl + o) = packbf2(v[0]-h0, v[1]-h1);
}

__global__ void bsum_build(const float* __restrict__ bl)
{
    int idx = blockIdx.x*blockDim.x + threadIdx.x;
    if (idx >= LL*HH) return;
    int l = idx / HH, j = idx % HH;
    float v = 0.f;
    #pragma unroll
    for (int r = 0; r < RR; r++) v += bl[(l*RR + r)*HH + j];
    g_bsum[idx] = v;
}

// ---------------- CSR build ----------------
__global__ void hist_kernel(const int* __restrict__ edges)
{
    int idx = blockIdx.x*blockDim.x + threadIdx.x;
    if (idx >= RR*EE) return;
    int r = idx / EE, e = idx % EE;
    atomicAdd(&g_cnt[r*NN + edges[(r*2 + 1)*EE + e]], 1);
}
__global__ void scan_kernel()
{
    int r = blockIdx.x;
    __shared__ int sh[1024];
    __shared__ int s_run;
    if (threadIdx.x == 0) s_run = 0;
    __syncthreads();
    for (int base = 0; base < NN; base += 1024){
        int i = base + threadIdx.x;
        int c = (i < NN) ? g_cnt[r*NN + i] : 0;
        sh[threadIdx.x] = c;
        __syncthreads();
        for (int d = 1; d < 1024; d <<= 1){
            int v = (threadIdx.x >= d) ? sh[threadIdx.x - d] : 0;
            __syncthreads();
            sh[threadIdx.x] += v;
            __syncthreads();
        }
        int excl = sh[threadIdx.x] - c;
        if (i < NN){
            int o = s_run + excl;
            g_off[r*NN + i] = o;
            g_cur[r*NN + i] = o;
            g_inv[r*NN + i] = 1.0f / fmaxf((float)c, 1.0f);
        }
        __syncthreads();
        if (threadIdx.x == 1023) s_run += sh[1023];
        __syncthreads();
    }
}
__global__ void fill_kernel(const int* __restrict__ edges)
{
    int idx = blockIdx.x*blockDim.x + threadIdx.x;
    if (idx >= RR*EE) return;
    int r = idx / EE, e = idx % EE;
    int src = edges[(r*2 + 0)*EE + e];
    int dst = edges[(r*2 + 1)*EE + e];
    int p = atomicAdd(&g_cur[r*NN + dst], 1);
    g_csr[r*EE + p] = src;
}

// ---------------- mean aggregation ----------------
// reads h = root region (cols 1536..2047) of cur; writes agg region (cols rel*512..)
__global__ __launch_bounds__(128) void agg2(const bf16* bh, const bf16* bl, bf16* wh, bf16* wl)
{
    const int node = blockIdx.x, rel = blockIdx.y, t = threadIdx.x;
    const int base = rel*NN + node;
    const int b = g_off[base], d = g_cnt[base];
    const int* lst = g_csr + (size_t)rel*EE + b;
    const int c = t*4;
    float a0 = 0.f, a1 = 0.f, a2 = 0.f, a3 = 0.f;
    for (int e = 0; e < d; e++){
        const int s = lst[e];
        const size_t off = (size_t)s*KCAT + RR*HH + c;
        uint2 hv = *(const uint2*)(bh + off);
        uint2 lv = *(const uint2*)(bl + off);
        float2 h01 = __bfloat1622float2(*(__nv_bfloat162*)&hv.x);
        float2 h23 = __bfloat1622float2(*(__nv_bfloat162*)&hv.y);
        float2 l01 = __bfloat1622float2(*(__nv_bfloat162*)&lv.x);
        float2 l23 = __bfloat1622float2(*(__nv_bfloat162*)&lv.y);
        a0 += h01.x + l01.x; a1 += h01.y + l01.y;
        a2 += h23.x + l23.x; a3 += h23.y + l23.y;
    }
    const float sc = g_inv[base];
    a0 *= sc; a1 *= sc; a2 *= sc; a3 *= sc;
    const float h0 = bfhi(a0), h1 = bfhi(a1), h2 = bfhi(a2), h3 = bfhi(a3);
    const size_t o = (size_t)node*KCAT + rel*HH + c;
    *(uint2*)(wh + o) = make_uint2(packbf2(h0,h1), packbf2(h2,h3));
    *(uint2*)(wl + o) = make_uint2(packbf2(a0-h0, a1-h1), packbf2(a2-h2, a3-h3));
}

// ------------------------------------------------------------------
extern "C" void kernel_launch(void* const* d_in, const int* in_sizes, int n_in,
                              void* d_out, int out_size)
{
    const float* x     = (const float*)d_in[0];
    const float* Wpre  = (const float*)d_in[1];
    const float* Wpost = (const float*)d_in[2];
    const float* Wl    = (const float*)d_in[3];
    const float* Wr    = (const float*)d_in[4];
    const float* bl    = (const float*)d_in[5];
    const float* Wout  = (const float*)d_in[6];
    const float* bout  = (const float*)d_in[7];
    const int*   edges = (const int*)d_in[8];
    float* out = (float*)d_out;

    cudaFuncSetAttribute(tc_gemm, cudaFuncAttributeMaxDynamicSharedMemorySize, SMEM_SZ);

    bf16 *xh,*xl,*t1h,*t1l,*Ph,*Pl,*Qh,*Ql;
    bf16 *wpreh,*wprel,*wposth,*wpostl,*wcath,*wcatl,*wouth,*woutl;
    float *bsum; int *cnt;
    cudaGetSymbolAddress((void**)&xh,  g_xh);    cudaGetSymbolAddress((void**)&xl,  g_xl);
    cudaGetSymbolAddress((void**)&t1h, g_t1h);   cudaGetSymbolAddress((void**)&t1l, g_t1l);
    cudaGetSymbolAddress((void**)&Ph,  g_Ph);    cudaGetSymbolAddress((void**)&Pl,  g_Pl);
    cudaGetSymbolAddress((void**)&Qh,  g_Qh);    cudaGetSymbolAddress((void**)&Ql,  g_Ql);
    cudaGetSymbolAddress((void**)&wpreh,  g_wpreh);   cudaGetSymbolAddress((void**)&wprel,  g_wprel);
    cudaGetSymbolAddress((void**)&wposth, g_wposth);  cudaGetSymbolAddress((void**)&wpostl, g_wpostl);
    cudaGetSymbolAddress((void**)&wcath,  g_wcath);   cudaGetSymbolAddress((void**)&wcatl,  g_wcatl);
    cudaGetSymbolAddress((void**)&wouth,  g_wouth);   cudaGetSymbolAddress((void**)&woutl,  g_woutl);
    cudaGetSymbolAddress((void**)&bsum, g_bsum);
    cudaGetSymbolAddress((void**)&cnt,  g_cnt);

    // operand packing
    conv_x<<<(NN*128 + 255)/256, 256>>>(x);
    wb_t<<<(HH*(HH/2) + 255)/256, 256>>>(Wpre,  wpreh,  wprel,  HH, HH, HH);
    wb_t<<<(HH*(HH/2) + 255)/256, 256>>>(Wpost, wposth, wpostl, HH, HH, HH);
    wb_t<<<(256*(HH/2) + 255)/256, 256>>>(Wout, wouth,  woutl,  HH, OUTC, 256);
    wb_cat<<<(LL*HH*(KCAT/2) + 255)/256, 256>>>(Wl, Wr);
    bsum_build<<<(LL*HH + 255)/256, 256>>>(bl);

    // CSR build
    cudaMemsetAsync(cnt, 0, (size_t)RR*NN*sizeof(int));
    hist_kernel<<<(RR*EE + 255)/256, 256>>>(edges);
    scan_kernel<<<RR, 1024>>>();
    fill_kernel<<<(RR*EE + 255)/256, 256>>>(edges);

    dim3 g4(4, MT), g2(2, MT);

    // h0 = leaky(leaky(x@Wpre)@Wpost) -> root region of P
    tc_gemm<<<g4, 256, SMEM_SZ>>>(xh, xl, HH, wpreh, wprel, HH,
                                  nullptr, 0, 1.f, 1,
                                  t1h, t1l, HH, 0, nullptr, 0, NN);
    tc_gemm<<<g4, 256, SMEM_SZ>>>(t1h, t1l, HH, wposth, wpostl, HH,
                                  nullptr, 0, 1.f, 1,
                                  Ph, Pl, KCAT, RR*HH, nullptr, 0, NN);

    bf16 *curh = Ph, *curl = Pl, *nxth = Qh, *nxtl = Ql;
    for (int l = 0; l < LL; l++){
        dim3 ga(NN, RR);
        agg2<<<ga, 128>>>(curh, curl, curh, curl);
        tc_gemm<<<g4, 256, SMEM_SZ>>>(curh, curl, KCAT,
                                      wcath + (size_t)l*HH*KCAT, wcatl + (size_t)l*HH*KCAT, KCAT,
                                      bsum + l*HH, HH, 1.f/3.f, 1,
                                      nxth, nxtl, KCAT, RR*HH, nullptr, 0, NN);
        bf16* th = curh; bf16* tl = curl;
        curh = nxth; curl = nxtl; nxth = th; nxtl = tl;
    }

    // out = h4 @ Wout + bout  (A = root region of cur)
    tc_gemm<<<g2, 256, SMEM_SZ>>>(curh + RR*HH, curl + RR*HH, KCAT,
                                  wouth, woutl, HH,
                                  bout, OUTC, 1.f, 0,
                                  nullptr, nullptr, 0, 0, out, OUTC, NN);
}